// round 4
// baseline (speedup 1.0000x reference)
#include <cuda_runtime.h>
#include <math.h>

#define Bn   64
#define Sn   512
#define EMBn 128
#define HIDn 256
#define G4   1024
#define NTAG 9
#define NBLK_LSTM 128
#define HS_STRIDE 260

// -------- persistent device scratch (no runtime allocs allowed) --------
__device__ float g_xz  [2u*Bn*Sn*G4];    // ((d*64+b)*512+s)*1024 + g     (256 MB)
__device__ float g_hall[2u*Bn*Sn*HIDn];  // ((d*64+b)*512+s)*256  + j     (64 MB)
__device__ int   g_lens[Bn];
__device__ unsigned g_bar;

__global__ void k_reset() { if (threadIdx.x == 0) g_bar = 0u; }

// ---------------- lens: count nonzero tokens per row -------------------
__global__ void k_lens(const int* __restrict__ text, float* __restrict__ out_lens) {
    int b = blockIdx.x, lane = threadIdx.x;     // 64 blocks x 32
    int cnt = 0;
    for (int s = lane; s < Sn; s += 32) cnt += (text[b*Sn + s] != 0);
    for (int o = 16; o > 0; o >>= 1) cnt += __shfl_down_sync(0xffffffffu, cnt, o);
    if (lane == 0) { g_lens[b] = cnt; out_lens[b] = (float)cnt; }
}

// ------------- input GEMM: xz = gather(emb,text) @ W + b  (both dirs) ---
// M = 32768 (b*512+s), K = 128, N = 2048 (dir*1024+g). 64x64 tiles, BK=64.
__global__ __launch_bounds__(256) void k_input_gemm(
    const int* __restrict__ text, const float* __restrict__ emb,
    const float* __restrict__ Wf, const float* __restrict__ bf,
    const float* __restrict__ Wb, const float* __restrict__ bb)
{
    __shared__ float A_s[64*64];   // [k][m] (transposed)
    __shared__ float B_s[64*64];   // [k][n]

    int m0 = blockIdx.y * 64;
    int n0 = blockIdx.x * 64;
    int d  = n0 >> 10;             // direction
    int gg0 = n0 - (d << 10);
    const float* W  = d ? Wb : Wf;
    const float* bs = d ? bb : bf;

    int tid = threadIdx.x;
    int tx = tid & 15, ty = tid >> 4;

    float c[4][4];
    #pragma unroll
    for (int i = 0; i < 4; i++)
        #pragma unroll
        for (int j = 0; j < 4; j++) c[i][j] = 0.f;

    int r  = tid >> 2, cq = tid & 3;
    int tok = text[m0 + r];
    const float* erow = emb + (long)tok * EMBn;

    for (int kt = 0; kt < 2; kt++) {
        __syncthreads();
        // A tile: gathered embedding rows, stored transposed [k][m]
        #pragma unroll
        for (int i = 0; i < 4; i++) {
            float4 v = *(const float4*)(erow + kt*64 + cq*16 + i*4);
            int kb = cq*16 + i*4;
            A_s[(kb+0)*64 + r] = v.x;
            A_s[(kb+1)*64 + r] = v.y;
            A_s[(kb+2)*64 + r] = v.z;
            A_s[(kb+3)*64 + r] = v.w;
        }
        // B tile: W rows [kt*64 .. +63], cols [gg0 .. +63]
        #pragma unroll
        for (int i = 0; i < 4; i++) {
            int kr = (tid >> 4) + i*16;
            float4 v = *(const float4*)(W + (long)(kt*64 + kr)*G4 + gg0 + (tid & 15)*4);
            *(float4*)&B_s[kr*64 + (tid & 15)*4] = v;
        }
        __syncthreads();

        #pragma unroll 8
        for (int k = 0; k < 64; k++) {
            float4 a  = *(float4*)&A_s[k*64 + ty*4];
            float4 b4 = *(float4*)&B_s[k*64 + tx*4];
            c[0][0] += a.x*b4.x; c[0][1] += a.x*b4.y; c[0][2] += a.x*b4.z; c[0][3] += a.x*b4.w;
            c[1][0] += a.y*b4.x; c[1][1] += a.y*b4.y; c[1][2] += a.y*b4.z; c[1][3] += a.y*b4.w;
            c[2][0] += a.z*b4.x; c[2][1] += a.z*b4.y; c[2][2] += a.z*b4.z; c[2][3] += a.z*b4.w;
            c[3][0] += a.w*b4.x; c[3][1] += a.w*b4.y; c[3][2] += a.w*b4.z; c[3][3] += a.w*b4.w;
        }
    }

    float4 bv = *(const float4*)(bs + gg0 + tx*4);
    #pragma unroll
    for (int i = 0; i < 4; i++) {
        long m = m0 + ty*4 + i;
        float4 o;
        o.x = c[i][0] + bv.x; o.y = c[i][1] + bv.y;
        o.z = c[i][2] + bv.z; o.w = c[i][3] + bv.w;
        *(float4*)&g_xz[((long)d*32768 + m)*G4 + gg0 + tx*4] = o;
    }
}

// ------------------- persistent bidirectional LSTM ----------------------
// 128 blocks: block = (dir, 4 hidden columns). Thread = (batch b, jj in 0..3),
// owns all 4 gates of hidden unit j = j0+jj; c-state stays in a register.
__global__ __launch_bounds__(256) void k_lstm(const float* __restrict__ Uf,
                                              const float* __restrict__ Ub)
{
    extern __shared__ float sm[];
    float* h_s = sm;                       // 64 * 260
    float* U_s = sm + 64*HS_STRIDE;        // 256 * 16 : [k][jj][gate]

    int blk = blockIdx.x;
    int d   = blk >> 6;
    int j0  = (blk & 63) * 4;
    int tid = threadIdx.x;
    int b   = tid >> 2, jj = tid & 3;
    const float* U = d ? Ub : Uf;

    // U slice: cols {g*256 + j0+jj : g=0..3, jj=0..3}, laid out [k][jj][g]
    for (int idx = tid; idx < 256*16; idx += 256) {
        int k = idx >> 4, cc = idx & 15;
        int jj_ = cc >> 2, g_ = cc & 3;
        U_s[idx] = U[k*G4 + g_*256 + j0 + jj_];
    }
    for (int i = tid; i < 64*HS_STRIDE; i += 256) h_s[i] = 0.f;

    float cstate = 0.f;
    long xzbase = ((long)(d*64 + b)) * Sn * G4;
    long hbase  = ((long)(d*64 + b)) * Sn * HIDn;
    int  boff   = b * HS_STRIDE;
    __syncthreads();

    for (int r = 0; r < Sn; r++) {
        int s = d ? (Sn-1-r) : r;
        if (r > 0) {
            int sp = d ? (s+1) : (s-1);
            #pragma unroll
            for (int i = 0; i < 16; i++) {
                int l  = i*256 + tid;           // float4 index over 64x64
                int lb = l >> 6, lj = (l & 63) << 2;
                float4 v = *(const float4*)&g_hall[(((long)(d*64 + lb))*Sn + sp)*HIDn + lj];
                *(float4*)&h_s[lb*HS_STRIDE + lj] = v;
            }
        }
        const float* xp = g_xz + xzbase + (long)s*G4 + j0 + jj;
        float x0 = __ldg(xp);
        float x1 = __ldg(xp + 256);
        float x2 = __ldg(xp + 512);
        float x3 = __ldg(xp + 768);
        __syncthreads();

        float ai = 0.f, af = 0.f, ag = 0.f, ao = 0.f;
        #pragma unroll 8
        for (int k = 0; k < 256; k += 4) {
            float4 h4 = *(float4*)&h_s[boff + k];
            float4 u;
            u = *(float4*)&U_s[(k+0)*16 + jj*4];
            ai += h4.x*u.x; af += h4.x*u.y; ag += h4.x*u.z; ao += h4.x*u.w;
            u = *(float4*)&U_s[(k+1)*16 + jj*4];
            ai += h4.y*u.x; af += h4.y*u.y; ag += h4.y*u.z; ao += h4.y*u.w;
            u = *(float4*)&U_s[(k+2)*16 + jj*4];
            ai += h4.z*u.x; af += h4.z*u.y; ag += h4.z*u.z; ao += h4.z*u.w;
            u = *(float4*)&U_s[(k+3)*16 + jj*4];
            ai += h4.w*u.x; af += h4.w*u.y; ag += h4.w*u.z; ao += h4.w*u.w;
        }
        float zi = x0 + ai, zf = x1 + af, zg = x2 + ag, zo = x3 + ao;
        float ig = 1.f / (1.f + __expf(-zi));
        float fg = 1.f / (1.f + __expf(-zf));
        float gv = tanhf(zg);
        float og = 1.f / (1.f + __expf(-zo));
        cstate = fg*cstate + ig*gv;
        float hv = og * tanhf(cstate);
        g_hall[hbase + (long)s*HIDn + j0 + jj] = hv;

        // grid barrier: all 128 blocks co-resident (<=148 SMs) by construction
        __threadfence();
        __syncthreads();
        if (tid == 0) {
            atomicAdd(&g_bar, 1u);
            unsigned target = (unsigned)(r + 1) * NBLK_LSTM;
            while (*((volatile unsigned*)&g_bar) < target) { }
        }
        __syncthreads();
    }
}

// ---------------- logits = [h_fwd ; h_bwd] @ W_d + b_d ------------------
__global__ __launch_bounds__(256) void k_logits(
    const float* __restrict__ Wd, const float* __restrict__ bd,
    float* __restrict__ out)
{
    __shared__ float Wd_s[512*NTAG];
    int tid = threadIdx.x;
    for (int i = tid; i < 512*NTAG; i += 256) Wd_s[i] = Wd[i];
    __syncthreads();

    int wid = tid >> 5, lane = tid & 31;
    long m = (long)blockIdx.x * 8 + wid;

    float acc[NTAG];
    #pragma unroll
    for (int t = 0; t < NTAG; t++) acc[t] = 0.f;

    for (int k = lane; k < 512; k += 32) {
        int dd = k >> 8, j = k & 255;
        float hv = g_hall[((long)dd*32768 + m)*HIDn + j];
        #pragma unroll
        for (int t = 0; t < NTAG; t++) acc[t] += hv * Wd_s[k*NTAG + t];
    }
    #pragma unroll
    for (int t = 0; t < NTAG; t++)
        for (int o = 16; o > 0; o >>= 1)
            acc[t] += __shfl_down_sync(0xffffffffu, acc[t], o);
    if (lane == 0) {
        #pragma unroll
        for (int t = 0; t < NTAG; t++) out[m*NTAG + t] = acc[t] + bd[t];
    }
}

// --------------------------- CRF (warp per batch) -----------------------
__global__ __launch_bounds__(256) void k_crf(
    const float* __restrict__ logits, const int* __restrict__ labels,
    const float* __restrict__ trans, float* __restrict__ out_ll)
{
    __shared__ float tr[81];
    __shared__ float alpha[8][12];
    int tid = threadIdx.x;
    if (tid < 81) tr[tid] = trans[tid];
    __syncthreads();

    int wid = tid >> 5, lane = tid & 31;
    int b = blockIdx.x * 8 + wid;
    int len = g_lens[b];
    const float* lg = logits + (long)b * Sn * NTAG;
    const int*   lb = labels + (long)b * Sn;

    // sequence score (unary + binary, masked)
    float sc = 0.f;
    for (int t = lane; t < Sn; t += 32) {
        int y = lb[t];
        if (t < len)     sc += lg[t*NTAG + y];
        if (t < len - 1) sc += tr[y*NTAG + lb[t+1]];
    }
    for (int o = 16; o > 0; o >>= 1) sc += __shfl_down_sync(0xffffffffu, sc, o);
    sc = __shfl_sync(0xffffffffu, sc, 0);

    // forward algorithm
    if (lane < NTAG) alpha[wid][lane] = lg[lane];
    __syncwarp();
    for (int t = 1; t < Sn; t++) {
        if (t >= len) break;                 // uniform per warp
        float na = 0.f;
        if (lane < NTAG) {
            float mx = -1e30f;
            #pragma unroll
            for (int i = 0; i < NTAG; i++) {
                float v = alpha[wid][i] + tr[i*NTAG + lane];
                mx = fmaxf(mx, v);
            }
            float s = 0.f;
            #pragma unroll
            for (int i = 0; i < NTAG; i++)
                s += __expf(alpha[wid][i] + tr[i*NTAG + lane] - mx);
            na = mx + __logf(s) + lg[t*NTAG + lane];
        }
        __syncwarp();
        if (lane < NTAG) alpha[wid][lane] = na;
        __syncwarp();
    }
    if (lane == 0) {
        float mx = -1e30f;
        for (int i = 0; i < NTAG; i++) mx = fmaxf(mx, alpha[wid][i]);
        float s = 0.f;
        for (int i = 0; i < NTAG; i++) s += __expf(alpha[wid][i] - mx);
        out_ll[b] = sc - (mx + __logf(s));
    }
}

// ----------------------------------------------------------------------
extern "C" void kernel_launch(void* const* d_in, const int* in_sizes, int n_in,
                              void* d_out, int out_size)
{
    const int*   text  = (const int*)  d_in[0];
    const int*   labels= (const int*)  d_in[1];
    const float* emb   = (const float*)d_in[2];
    const float* Wf    = (const float*)d_in[3];
    const float* Uf    = (const float*)d_in[4];
    const float* bf    = (const float*)d_in[5];
    const float* Wb    = (const float*)d_in[6];
    const float* Ub    = (const float*)d_in[7];
    const float* bb    = (const float*)d_in[8];
    const float* Wd    = (const float*)d_in[9];
    const float* bd    = (const float*)d_in[10];
    const float* trans = (const float*)d_in[11];

    float* out        = (float*)d_out;
    float* out_logits = out;                         // 64*512*9
    float* out_lens   = out + 64ll*512*9;            // 64
    float* out_ll     = out_lens + 64;               // 64

    const int lstm_smem = (64*HS_STRIDE + 256*16) * 4;   // 82944 B
    cudaFuncSetAttribute(k_lstm, cudaFuncAttributeMaxDynamicSharedMemorySize, lstm_smem);

    k_reset<<<1, 32>>>();
    k_lens<<<64, 32>>>(text, out_lens);
    dim3 gg(32, 512);
    k_input_gemm<<<gg, 256>>>(text, emb, Wf, bf, Wb, bb);
    k_lstm<<<NBLK_LSTM, 256, lstm_smem>>>(Uf, Ub);
    k_logits<<<4096, 256>>>(Wd, bd, out_logits);
    k_crf<<<8, 256>>>(out_logits, labels, trans, out_ll);
}

// round 5
// speedup vs baseline: 1.0161x; 1.0161x over previous
#include <cuda_runtime.h>
#include <math.h>

#define Bn   64
#define Sn   512
#define EMBn 128
#define HIDn 256
#define G4   1024
#define NTAG 9
#define NBLK_LSTM 128
#define HS_STRIDE 260

// -------- persistent device scratch (no runtime allocs allowed) --------
__device__ float g_xz  [2u*Bn*Sn*G4];    // ((d*64+b)*512+s)*1024 + g     (256 MB)
__device__ float g_hall[2u*Bn*Sn*HIDn];  // ((d*64+b)*512+s)*256  + j     (64 MB)
__device__ int   g_lens[Bn];
__device__ unsigned g_bar;

__global__ void k_reset() { if (threadIdx.x == 0) g_bar = 0u; }

// f32x2 packed helpers (sm_100+ PTX; ptxas never auto-fuses these)
__device__ __forceinline__ void ffma2(unsigned long long& acc,
                                      unsigned long long a,
                                      unsigned long long b) {
    asm("fma.rn.f32x2 %0, %1, %2, %0;" : "+l"(acc) : "l"(a), "l"(b));
}
__device__ __forceinline__ unsigned long long dup2(float x) {
    unsigned long long r;
    asm("mov.b64 %0, {%1, %1};" : "=l"(r) : "f"(x));
    return r;
}
__device__ __forceinline__ float2 unpack2(unsigned long long v) {
    float2 r;
    asm("mov.b64 {%0, %1}, %2;" : "=f"(r.x), "=f"(r.y) : "l"(v));
    return r;
}

// ---------------- lens: count nonzero tokens per row -------------------
__global__ void k_lens(const int* __restrict__ text, float* __restrict__ out_lens) {
    int b = blockIdx.x, lane = threadIdx.x;     // 64 blocks x 32
    int cnt = 0;
    for (int s = lane; s < Sn; s += 32) cnt += (text[b*Sn + s] != 0);
    for (int o = 16; o > 0; o >>= 1) cnt += __shfl_down_sync(0xffffffffu, cnt, o);
    if (lane == 0) { g_lens[b] = cnt; out_lens[b] = (float)cnt; }
}

// ------------- input GEMM: xz = gather(emb,text) @ W + b  (both dirs) ---
// M = 32768 (b*512+s), K = 128, N = 2048 (dir*1024+g). 64x64 tiles, BK=64.
// Inner product via packed fma.rn.f32x2 (pairs along n).
__global__ __launch_bounds__(256) void k_input_gemm(
    const int* __restrict__ text, const float* __restrict__ emb,
    const float* __restrict__ Wf, const float* __restrict__ bf,
    const float* __restrict__ Wb, const float* __restrict__ bb)
{
    __shared__ float A_s[64*64];   // [k][m] (transposed)
    __shared__ float B_s[64*64];   // [k][n]

    int m0 = blockIdx.y * 64;
    int n0 = blockIdx.x * 64;
    int d  = n0 >> 10;             // direction
    int gg0 = n0 - (d << 10);
    const float* W  = d ? Wb : Wf;
    const float* bs = d ? bb : bf;

    int tid = threadIdx.x;
    int tx = tid & 15, ty = tid >> 4;

    unsigned long long c2[4][2];
    #pragma unroll
    for (int i = 0; i < 4; i++) { c2[i][0] = 0ull; c2[i][1] = 0ull; }

    int r  = tid >> 2, cq = tid & 3;
    int tok = text[m0 + r];
    const float* erow = emb + (long)tok * EMBn;

    for (int kt = 0; kt < 2; kt++) {
        __syncthreads();
        // A tile: gathered embedding rows, stored transposed [k][m]
        #pragma unroll
        for (int i = 0; i < 4; i++) {
            float4 v = *(const float4*)(erow + kt*64 + cq*16 + i*4);
            int kb = cq*16 + i*4;
            A_s[(kb+0)*64 + r] = v.x;
            A_s[(kb+1)*64 + r] = v.y;
            A_s[(kb+2)*64 + r] = v.z;
            A_s[(kb+3)*64 + r] = v.w;
        }
        // B tile: W rows [kt*64 .. +63], cols [gg0 .. +63]
        #pragma unroll
        for (int i = 0; i < 4; i++) {
            int kr = (tid >> 4) + i*16;
            float4 v = *(const float4*)(W + (long)(kt*64 + kr)*G4 + gg0 + (tid & 15)*4);
            *(float4*)&B_s[kr*64 + (tid & 15)*4] = v;
        }
        __syncthreads();

        #pragma unroll 8
        for (int k = 0; k < 64; k++) {
            float4 a = *(float4*)&A_s[k*64 + ty*4];
            ulonglong2 bu = *(ulonglong2*)&B_s[k*64 + tx*4];
            unsigned long long ad;
            ad = dup2(a.x); ffma2(c2[0][0], ad, bu.x); ffma2(c2[0][1], ad, bu.y);
            ad = dup2(a.y); ffma2(c2[1][0], ad, bu.x); ffma2(c2[1][1], ad, bu.y);
            ad = dup2(a.z); ffma2(c2[2][0], ad, bu.x); ffma2(c2[2][1], ad, bu.y);
            ad = dup2(a.w); ffma2(c2[3][0], ad, bu.x); ffma2(c2[3][1], ad, bu.y);
        }
    }

    float4 bv = *(const float4*)(bs + gg0 + tx*4);
    #pragma unroll
    for (int i = 0; i < 4; i++) {
        long m = m0 + ty*4 + i;
        float2 lo = unpack2(c2[i][0]);
        float2 hi = unpack2(c2[i][1]);
        float4 o;
        o.x = lo.x + bv.x; o.y = lo.y + bv.y;
        o.z = hi.x + bv.z; o.w = hi.y + bv.w;
        *(float4*)&g_xz[((long)d*32768 + m)*G4 + gg0 + tx*4] = o;
    }
}

// ------------------- persistent bidirectional LSTM ----------------------
// 128 blocks x 512 threads: block = (dir, 4 hidden cols). Thread = (kh, b, jj):
// kh in {0,1} splits the 256-wide k-reduction; (b,jj) owns all 4 gates of
// hidden unit j0+jj via two packed f32x2 accumulators. c-state lives in a
// register of the kh==0 thread.
__global__ __launch_bounds__(512) void k_lstm(const float* __restrict__ Uf,
                                              const float* __restrict__ Ub)
{
    extern __shared__ float sm[];
    float* h_s  = sm;                        // 64 * 260
    float* U_s  = sm + 64*HS_STRIDE;         // 256 * 16 : [k][jj][gate]
    unsigned long long* red = (unsigned long long*)(sm + 64*HS_STRIDE + 256*16); // 256*2

    int blk = blockIdx.x;
    int d   = blk >> 6;
    int j0  = (blk & 63) * 4;
    int tid = threadIdx.x;
    int kh  = tid >> 8;          // k-half
    int r8  = tid & 255;
    int b   = r8 >> 2, jj = r8 & 3;
    const float* U = d ? Ub : Uf;

    // U slice: cols {g*256 + j0+jj : g=0..3, jj=0..3}, laid out [k][jj][gate]
    for (int idx = tid; idx < 256*16; idx += 512) {
        int k = idx >> 4, cc = idx & 15;
        int jj_ = cc >> 2, g_ = cc & 3;
        U_s[idx] = U[k*G4 + g_*256 + j0 + jj_];
    }
    for (int i = tid; i < 64*HS_STRIDE; i += 512) h_s[i] = 0.f;

    float cstate = 0.f;
    long xzbase = ((long)(d*64 + b)) * Sn * G4;
    long hbase  = ((long)(d*64 + b)) * Sn * HIDn;
    int  boff   = b * HS_STRIDE;
    int  k0     = kh << 7;
    __syncthreads();

    for (int r = 0; r < Sn; r++) {
        int s = d ? (Sn-1-r) : r;

        float x0, x1, x2, x3;
        if (kh == 0) {
            const float* xp = g_xz + xzbase + (long)s*G4 + j0 + jj;
            x0 = __ldg(xp);
            x1 = __ldg(xp + 256);
            x2 = __ldg(xp + 512);
            x3 = __ldg(xp + 768);
        }
        if (r > 0) {
            int sp = d ? (s+1) : (s-1);
            #pragma unroll
            for (int i = 0; i < 8; i++) {
                int l  = i*512 + tid;           // float4 index over 64x64
                int lb = l >> 6, lj = (l & 63) << 2;
                float4 v = *(const float4*)&g_hall[(((long)(d*64 + lb))*Sn + sp)*HIDn + lj];
                *(float4*)&h_s[lb*HS_STRIDE + lj] = v;
            }
        }
        __syncthreads();

        unsigned long long a_if = 0ull, a_go = 0ull;
        #pragma unroll 8
        for (int kk = 0; kk < 128; kk += 4) {
            int k = k0 + kk;
            float4 h4 = *(float4*)&h_s[boff + k];
            ulonglong2 u;
            unsigned long long hd;
            u = *(ulonglong2*)&U_s[(k+0)*16 + jj*4];
            hd = dup2(h4.x); ffma2(a_if, hd, u.x); ffma2(a_go, hd, u.y);
            u = *(ulonglong2*)&U_s[(k+1)*16 + jj*4];
            hd = dup2(h4.y); ffma2(a_if, hd, u.x); ffma2(a_go, hd, u.y);
            u = *(ulonglong2*)&U_s[(k+2)*16 + jj*4];
            hd = dup2(h4.z); ffma2(a_if, hd, u.x); ffma2(a_go, hd, u.y);
            u = *(ulonglong2*)&U_s[(k+3)*16 + jj*4];
            hd = dup2(h4.w); ffma2(a_if, hd, u.x); ffma2(a_go, hd, u.y);
        }

        // cross-half reduce: kh==1 deposits, kh==0 combines
        if (kh == 1) {
            red[r8*2 + 0] = a_if;
            red[r8*2 + 1] = a_go;
        }
        __syncthreads();

        if (kh == 0) {
            float2 p_if = unpack2(a_if), q_if = unpack2(red[r8*2 + 0]);
            float2 p_go = unpack2(a_go), q_go = unpack2(red[r8*2 + 1]);
            float zi = x0 + p_if.x + q_if.x;
            float zf = x1 + p_if.y + q_if.y;
            float zg = x2 + p_go.x + q_go.x;
            float zo = x3 + p_go.y + q_go.y;
            float ig = 1.f / (1.f + __expf(-zi));
            float fg = 1.f / (1.f + __expf(-zf));
            float gv = tanhf(zg);
            float og = 1.f / (1.f + __expf(-zo));
            cstate = fg*cstate + ig*gv;
            float hv = og * tanhf(cstate);
            g_hall[hbase + (long)s*HIDn + j0 + jj] = hv;
        }

        // grid barrier: all 128 blocks co-resident (<=148 SMs) by construction
        __threadfence();
        __syncthreads();
        if (tid == 0) {
            atomicAdd(&g_bar, 1u);
            unsigned target = (unsigned)(r + 1) * NBLK_LSTM;
            while (*((volatile unsigned*)&g_bar) < target) { }
        }
        __syncthreads();
    }
}

// ---------------- logits = [h_fwd ; h_bwd] @ W_d + b_d ------------------
__global__ __launch_bounds__(256) void k_logits(
    const float* __restrict__ Wd, const float* __restrict__ bd,
    float* __restrict__ out)
{
    __shared__ float Wd_s[512*NTAG];
    int tid = threadIdx.x;
    for (int i = tid; i < 512*NTAG; i += 256) Wd_s[i] = Wd[i];
    __syncthreads();

    int wid = tid >> 5, lane = tid & 31;
    long m = (long)blockIdx.x * 8 + wid;

    float acc[NTAG];
    #pragma unroll
    for (int t = 0; t < NTAG; t++) acc[t] = 0.f;

    for (int k = lane; k < 512; k += 32) {
        int dd = k >> 8, j = k & 255;
        float hv = g_hall[((long)dd*32768 + m)*HIDn + j];
        #pragma unroll
        for (int t = 0; t < NTAG; t++) acc[t] += hv * Wd_s[k*NTAG + t];
    }
    #pragma unroll
    for (int t = 0; t < NTAG; t++)
        for (int o = 16; o > 0; o >>= 1)
            acc[t] += __shfl_down_sync(0xffffffffu, acc[t], o);
    if (lane == 0) {
        #pragma unroll
        for (int t = 0; t < NTAG; t++) out[m*NTAG + t] = acc[t] + bd[t];
    }
}

// --------------------------- CRF (warp per batch) -----------------------
__global__ __launch_bounds__(256) void k_crf(
    const float* __restrict__ logits, const int* __restrict__ labels,
    const float* __restrict__ trans, float* __restrict__ out_ll)
{
    __shared__ float tr[81];
    __shared__ float alpha[8][12];
    int tid = threadIdx.x;
    if (tid < 81) tr[tid] = trans[tid];
    __syncthreads();

    int wid = tid >> 5, lane = tid & 31;
    int b = blockIdx.x * 8 + wid;
    int len = g_lens[b];
    const float* lg = logits + (long)b * Sn * NTAG;
    const int*   lb = labels + (long)b * Sn;

    // sequence score (unary + binary, masked)
    float sc = 0.f;
    for (int t = lane; t < Sn; t += 32) {
        int y = lb[t];
        if (t < len)     sc += lg[t*NTAG + y];
        if (t < len - 1) sc += tr[y*NTAG + lb[t+1]];
    }
    for (int o = 16; o > 0; o >>= 1) sc += __shfl_down_sync(0xffffffffu, sc, o);
    sc = __shfl_sync(0xffffffffu, sc, 0);

    // forward algorithm
    if (lane < NTAG) alpha[wid][lane] = lg[lane];
    __syncwarp();
    for (int t = 1; t < Sn; t++) {
        if (t >= len) break;                 // uniform per warp
        float na = 0.f;
        if (lane < NTAG) {
            float mx = -1e30f;
            #pragma unroll
            for (int i = 0; i < NTAG; i++) {
                float v = alpha[wid][i] + tr[i*NTAG + lane];
                mx = fmaxf(mx, v);
            }
            float s = 0.f;
            #pragma unroll
            for (int i = 0; i < NTAG; i++)
                s += __expf(alpha[wid][i] + tr[i*NTAG + lane] - mx);
            na = mx + __logf(s) + lg[t*NTAG + lane];
        }
        __syncwarp();
        if (lane < NTAG) alpha[wid][lane] = na;
        __syncwarp();
    }
    if (lane == 0) {
        float mx = -1e30f;
        for (int i = 0; i < NTAG; i++) mx = fmaxf(mx, alpha[wid][i]);
        float s = 0.f;
        for (int i = 0; i < NTAG; i++) s += __expf(alpha[wid][i] - mx);
        out_ll[b] = sc - (mx + __logf(s));
    }
}

// ----------------------------------------------------------------------
extern "C" void kernel_launch(void* const* d_in, const int* in_sizes, int n_in,
                              void* d_out, int out_size)
{
    const int*   text  = (const int*)  d_in[0];
    const int*   labels= (const int*)  d_in[1];
    const float* emb   = (const float*)d_in[2];
    const float* Wf    = (const float*)d_in[3];
    const float* Uf    = (const float*)d_in[4];
    const float* bf    = (const float*)d_in[5];
    const float* Wb    = (const float*)d_in[6];
    const float* Ub    = (const float*)d_in[7];
    const float* bb    = (const float*)d_in[8];
    const float* Wd    = (const float*)d_in[9];
    const float* bd    = (const float*)d_in[10];
    const float* trans = (const float*)d_in[11];

    float* out        = (float*)d_out;
    float* out_logits = out;                         // 64*512*9
    float* out_lens   = out + 64ll*512*9;            // 64
    float* out_ll     = out_lens + 64;               // 64

    const int lstm_smem = (64*HS_STRIDE + 256*16) * 4 + 256*16;   // 87040 B
    cudaFuncSetAttribute(k_lstm, cudaFuncAttributeMaxDynamicSharedMemorySize, lstm_smem);

    k_reset<<<1, 32>>>();
    k_lens<<<64, 32>>>(text, out_lens);
    dim3 gg(32, 512);
    k_input_gemm<<<gg, 256>>>(text, emb, Wf, bf, Wb, bb);
    k_lstm<<<NBLK_LSTM, 512, lstm_smem>>>(Uf, Ub);
    k_logits<<<4096, 256>>>(Wd, bd, out_logits);
    k_crf<<<8, 256>>>(out_logits, labels, trans, out_ll);
}

// round 6
// speedup vs baseline: 1.6709x; 1.6444x over previous
#include <cuda_runtime.h>
#include <math.h>

#define Bn   64
#define Sn   512
#define EMBn 128
#define HIDn 256
#define G4   1024
#define NTAG 9
#define HS_STRIDE 260

// -------- persistent device scratch (no runtime allocs allowed) --------
__device__ float g_xz  [2u*Bn*Sn*G4];    // ((d*64+b)*512+s)*1024 + g
__device__ float g_hall[2u*Bn*Sn*HIDn];  // ((d*64+b)*512+s)*256  + j
__device__ int   g_lens[Bn];
__device__ unsigned g_bars[8*32];        // 8 group counters, 128B apart

__global__ void k_reset() {
    int t = threadIdx.x;
    if (t < 8*32) g_bars[t] = 0u;
}

// f32x2 packed helpers
__device__ __forceinline__ void ffma2(unsigned long long& acc,
                                      unsigned long long a,
                                      unsigned long long b) {
    asm("fma.rn.f32x2 %0, %1, %2, %0;" : "+l"(acc) : "l"(a), "l"(b));
}
__device__ __forceinline__ unsigned long long dup2(float x) {
    unsigned long long r;
    asm("mov.b64 %0, {%1, %1};" : "=l"(r) : "f"(x));
    return r;
}
__device__ __forceinline__ float2 unpack2(unsigned long long v) {
    float2 r;
    asm("mov.b64 {%0, %1}, %2;" : "=f"(r.x), "=f"(r.y) : "l"(v));
    return r;
}

// ---------------- lens: count nonzero tokens per row -------------------
__global__ void k_lens(const int* __restrict__ text, float* __restrict__ out_lens) {
    int b = blockIdx.x, lane = threadIdx.x;
    int cnt = 0;
    for (int s = lane; s < Sn; s += 32) cnt += (text[b*Sn + s] != 0);
    for (int o = 16; o > 0; o >>= 1) cnt += __shfl_down_sync(0xffffffffu, cnt, o);
    if (lane == 0) { g_lens[b] = cnt; out_lens[b] = (float)cnt; }
}

// ------------- input GEMM: xz = gather(emb,text) @ W + b  (both dirs) ---
__global__ __launch_bounds__(256) void k_input_gemm(
    const int* __restrict__ text, const float* __restrict__ emb,
    const float* __restrict__ Wf, const float* __restrict__ bf,
    const float* __restrict__ Wb, const float* __restrict__ bb)
{
    __shared__ float A_s[64*64];   // [k][m]
    __shared__ float B_s[64*64];   // [k][n]

    int m0 = blockIdx.y * 64;
    int n0 = blockIdx.x * 64;
    int d  = n0 >> 10;
    int gg0 = n0 - (d << 10);
    const float* W  = d ? Wb : Wf;
    const float* bs = d ? bb : bf;

    int tid = threadIdx.x;
    int tx = tid & 15, ty = tid >> 4;

    unsigned long long c2[4][2];
    #pragma unroll
    for (int i = 0; i < 4; i++) { c2[i][0] = 0ull; c2[i][1] = 0ull; }

    int r  = tid >> 2, cq = tid & 3;
    int tok = text[m0 + r];
    const float* erow = emb + (long)tok * EMBn;

    for (int kt = 0; kt < 2; kt++) {
        __syncthreads();
        #pragma unroll
        for (int i = 0; i < 4; i++) {
            float4 v = *(const float4*)(erow + kt*64 + cq*16 + i*4);
            int kb = cq*16 + i*4;
            A_s[(kb+0)*64 + r] = v.x;
            A_s[(kb+1)*64 + r] = v.y;
            A_s[(kb+2)*64 + r] = v.z;
            A_s[(kb+3)*64 + r] = v.w;
        }
        #pragma unroll
        for (int i = 0; i < 4; i++) {
            int kr = (tid >> 4) + i*16;
            float4 v = *(const float4*)(W + (long)(kt*64 + kr)*G4 + gg0 + (tid & 15)*4);
            *(float4*)&B_s[kr*64 + (tid & 15)*4] = v;
        }
        __syncthreads();

        #pragma unroll 8
        for (int k = 0; k < 64; k++) {
            float4 a = *(float4*)&A_s[k*64 + ty*4];
            ulonglong2 bu = *(ulonglong2*)&B_s[k*64 + tx*4];
            unsigned long long ad;
            ad = dup2(a.x); ffma2(c2[0][0], ad, bu.x); ffma2(c2[0][1], ad, bu.y);
            ad = dup2(a.y); ffma2(c2[1][0], ad, bu.x); ffma2(c2[1][1], ad, bu.y);
            ad = dup2(a.z); ffma2(c2[2][0], ad, bu.x); ffma2(c2[2][1], ad, bu.y);
            ad = dup2(a.w); ffma2(c2[3][0], ad, bu.x); ffma2(c2[3][1], ad, bu.y);
        }
    }

    float4 bv = *(const float4*)(bs + gg0 + tx*4);
    #pragma unroll
    for (int i = 0; i < 4; i++) {
        long m = m0 + ty*4 + i;
        float2 lo = unpack2(c2[i][0]);
        float2 hi = unpack2(c2[i][1]);
        float4 o;
        o.x = lo.x + bv.x; o.y = lo.y + bv.y;
        o.z = hi.x + bv.z; o.w = hi.y + bv.w;
        *(float4*)&g_xz[((long)d*32768 + m)*G4 + gg0 + tx*4] = o;
    }
}

// ------------------- persistent bidirectional LSTM ----------------------
// 128 blocks: blk = d*64 + hg*4 + bg.  Block owns dir d, hidden units
// [hg*16, hg*16+16), batches [bg*16, bg*16+16). U slice (64 KB) in smem.
// h exchange + barrier only among the 16 blocks sharing (d, bg).
// 512 threads = (kh 0..7) x (bq 0..3) x (j 0..15); each thread: 32-k slice,
// 4 batches, hidden unit j (4 gates via two f32x2 accumulators).
__global__ __launch_bounds__(512) void k_lstm(const float* __restrict__ Uf,
                                              const float* __restrict__ Ub)
{
    extern __shared__ float sm[];
    float* h_s = sm;                                   // 16 * 260
    float* U_s = sm + 16*HS_STRIDE;                    // 256*16*4 : [k][j][gate]
    unsigned long long* red = (unsigned long long*)(U_s + 256*64);  // 256*18 u64

    int blk = blockIdx.x;
    int d   = blk >> 6;
    int hg  = (blk >> 2) & 15;
    int bg  = blk & 3;
    int j0  = hg * 16;
    int b0  = bg * 16;
    int gid = d*4 + bg;                 // barrier group (16 members)

    int tid = threadIdx.x;
    int j   = tid & 15;
    int bq  = (tid >> 4) & 3;
    int kh  = tid >> 6;
    int k0  = kh << 5;
    const float* U = d ? Ub : Uf;

    // U slice -> smem: U_s[(k*16 + jy)*4 + g] = U[k*1024 + g*256 + j0 + jy]
    for (int idx = tid; idx < 256*64; idx += 512) {
        int k  = idx >> 6;
        int jy = (idx >> 2) & 15;
        int g  = idx & 3;
        U_s[idx] = U[k*G4 + g*256 + j0 + jy];
    }
    for (int i = tid; i < 16*HS_STRIDE; i += 512) h_s[i] = 0.f;

    float cstate = 0.f;                  // used by tid<256 (b = tid>>4, unit j)
    __syncthreads();

    for (int r = 0; r < Sn; r++) {
        int s = d ? (Sn-1-r) : r;

        // prefetch x for the gates this thread will finalize (tid<256)
        float x0, x1, x2, x3;
        if (tid < 256) {
            int fb = tid >> 4;
            const float* xp = g_xz + ((long)(d*64 + b0 + fb)*Sn + s)*G4 + j0 + j;
            x0 = __ldg(xp);
            x1 = __ldg(xp + 256);
            x2 = __ldg(xp + 512);
            x3 = __ldg(xp + 768);
        }
        // refill h_s from the group's previous-step output
        if (r > 0) {
            int sp = d ? (s+1) : (s-1);
            #pragma unroll
            for (int i = 0; i < 2; i++) {
                int l  = i*512 + tid;          // 1024 float4 = 16 x 64
                int lb = l >> 6, lj = (l & 63) << 2;
                float4 v = *(const float4*)&g_hall[(((long)(d*64 + b0 + lb))*Sn + sp)*HIDn + lj];
                *(float4*)&h_s[lb*HS_STRIDE + lj] = v;
            }
        }
        __syncthreads();

        unsigned long long acc[4][2];
        #pragma unroll
        for (int i = 0; i < 4; i++) { acc[i][0] = 0ull; acc[i][1] = 0ull; }

        #pragma unroll 4
        for (int kk = 0; kk < 32; kk += 4) {
            int k = k0 + kk;
            float hrow[4][4];
            #pragma unroll
            for (int i = 0; i < 4; i++) {
                float4 v = *(float4*)&h_s[(bq*4 + i)*HS_STRIDE + k];
                hrow[i][0] = v.x; hrow[i][1] = v.y; hrow[i][2] = v.z; hrow[i][3] = v.w;
            }
            #pragma unroll
            for (int t = 0; t < 4; t++) {
                ulonglong2 u = *(ulonglong2*)&U_s[(k + t)*64 + j*4];
                #pragma unroll
                for (int i = 0; i < 4; i++) {
                    unsigned long long hd = dup2(hrow[i][t]);
                    ffma2(acc[i][0], hd, u.x);
                    ffma2(acc[i][1], hd, u.y);
                }
            }
        }

        // deposit partials: red[bj*18 + kh*2] (stride 144B -> bank-spread)
        #pragma unroll
        for (int i = 0; i < 4; i++) {
            int bj = (bq*4 + i)*16 + j;
            ulonglong2 v; v.x = acc[i][0]; v.y = acc[i][1];
            *(ulonglong2*)&red[bj*18 + kh*2] = v;
        }
        __syncthreads();

        // finalize: 256 threads, one (batch, unit) each
        if (tid < 256) {
            float zi = x0, zf = x1, zg = x2, zo = x3;
            #pragma unroll
            for (int q = 0; q < 8; q++) {
                ulonglong2 v = *(ulonglong2*)&red[tid*18 + q*2];
                float2 pif = unpack2(v.x), pgo = unpack2(v.y);
                zi += pif.x; zf += pif.y; zg += pgo.x; zo += pgo.y;
            }
            float ig = 1.f / (1.f + __expf(-zi));
            float fg = 1.f / (1.f + __expf(-zf));
            float gv = tanhf(zg);
            float og = 1.f / (1.f + __expf(-zo));
            cstate = fg*cstate + ig*gv;
            float hv = og * tanhf(cstate);
            int fb = tid >> 4;
            g_hall[(((long)(d*64 + b0 + fb))*Sn + s)*HIDn + j0 + j] = hv;
        }

        // group barrier: 16 blocks sharing (d, bg); all co-resident
        __threadfence();
        __syncthreads();
        if (tid == 0) {
            atomicAdd(&g_bars[gid*32], 1u);
            unsigned target = (unsigned)(r + 1) * 16u;
            while (*((volatile unsigned*)&g_bars[gid*32]) < target) { }
        }
        __syncthreads();
    }
}

// ---------------- logits = [h_fwd ; h_bwd] @ W_d + b_d ------------------
__global__ __launch_bounds__(256) void k_logits(
    const float* __restrict__ Wd, const float* __restrict__ bd,
    float* __restrict__ out)
{
    __shared__ float Wd_s[512*NTAG];
    int tid = threadIdx.x;
    for (int i = tid; i < 512*NTAG; i += 256) Wd_s[i] = Wd[i];
    __syncthreads();

    int wid = tid >> 5, lane = tid & 31;
    long m = (long)blockIdx.x * 8 + wid;

    float acc[NTAG];
    #pragma unroll
    for (int t = 0; t < NTAG; t++) acc[t] = 0.f;

    for (int k = lane; k < 512; k += 32) {
        int dd = k >> 8, jj = k & 255;
        float hv = g_hall[((long)dd*32768 + m)*HIDn + jj];
        #pragma unroll
        for (int t = 0; t < NTAG; t++) acc[t] += hv * Wd_s[k*NTAG + t];
    }
    #pragma unroll
    for (int t = 0; t < NTAG; t++)
        for (int o = 16; o > 0; o >>= 1)
            acc[t] += __shfl_down_sync(0xffffffffu, acc[t], o);
    if (lane == 0) {
        #pragma unroll
        for (int t = 0; t < NTAG; t++) out[m*NTAG + t] = acc[t] + bd[t];
    }
}

// --------------------------- CRF (warp per batch) -----------------------
__global__ __launch_bounds__(256) void k_crf(
    const float* __restrict__ logits, const int* __restrict__ labels,
    const float* __restrict__ trans, float* __restrict__ out_ll)
{
    __shared__ float tr[81];
    __shared__ float alpha[8][12];
    int tid = threadIdx.x;
    if (tid < 81) tr[tid] = trans[tid];
    __syncthreads();

    int wid = tid >> 5, lane = tid & 31;
    int b = blockIdx.x * 8 + wid;
    int len = g_lens[b];
    const float* lg = logits + (long)b * Sn * NTAG;
    const int*   lb = labels + (long)b * Sn;

    float sc = 0.f;
    for (int t = lane; t < Sn; t += 32) {
        int y = lb[t];
        if (t < len)     sc += lg[t*NTAG + y];
        if (t < len - 1) sc += tr[y*NTAG + lb[t+1]];
    }
    for (int o = 16; o > 0; o >>= 1) sc += __shfl_down_sync(0xffffffffu, sc, o);
    sc = __shfl_sync(0xffffffffu, sc, 0);

    if (lane < NTAG) alpha[wid][lane] = lg[lane];
    __syncwarp();
    for (int t = 1; t < Sn; t++) {
        if (t >= len) break;
        float na = 0.f;
        if (lane < NTAG) {
            float mx = -1e30f;
            #pragma unroll
            for (int i = 0; i < NTAG; i++) {
                float v = alpha[wid][i] + tr[i*NTAG + lane];
                mx = fmaxf(mx, v);
            }
            float s = 0.f;
            #pragma unroll
            for (int i = 0; i < NTAG; i++)
                s += __expf(alpha[wid][i] + tr[i*NTAG + lane] - mx);
            na = mx + __logf(s) + lg[t*NTAG + lane];
        }
        __syncwarp();
        if (lane < NTAG) alpha[wid][lane] = na;
        __syncwarp();
    }
    if (lane == 0) {
        float mx = -1e30f;
        for (int i = 0; i < NTAG; i++) mx = fmaxf(mx, alpha[wid][i]);
        float s = 0.f;
        for (int i = 0; i < NTAG; i++) s += __expf(alpha[wid][i] - mx);
        out_ll[b] = sc - (mx + __logf(s));
    }
}

// ----------------------------------------------------------------------
extern "C" void kernel_launch(void* const* d_in, const int* in_sizes, int n_in,
                              void* d_out, int out_size)
{
    const int*   text  = (const int*)  d_in[0];
    const int*   labels= (const int*)  d_in[1];
    const float* emb   = (const float*)d_in[2];
    const float* Wf    = (const float*)d_in[3];
    const float* Uf    = (const float*)d_in[4];
    const float* bf    = (const float*)d_in[5];
    const float* Wb    = (const float*)d_in[6];
    const float* Ub    = (const float*)d_in[7];
    const float* bb    = (const float*)d_in[8];
    const float* Wd    = (const float*)d_in[9];
    const float* bd    = (const float*)d_in[10];
    const float* trans = (const float*)d_in[11];

    float* out        = (float*)d_out;
    float* out_logits = out;                         // 64*512*9
    float* out_lens   = out + 64ll*512*9;            // 64
    float* out_ll     = out_lens + 64;               // 64

    // smem: h_s 16*260*4 + U_s 64KB + red 256*18*8 = 16640+65536+36864
    const int lstm_smem = 16*HS_STRIDE*4 + 256*64*4 + 256*18*8;   // 119040 B
    cudaFuncSetAttribute(k_lstm, cudaFuncAttributeMaxDynamicSharedMemorySize, lstm_smem);

    k_reset<<<1, 256>>>();
    k_lens<<<64, 32>>>(text, out_lens);
    dim3 gg(32, 512);
    k_input_gemm<<<gg, 256>>>(text, emb, Wf, bf, Wb, bb);
    k_lstm<<<128, 512, lstm_smem>>>(Uf, Ub);
    k_logits<<<4096, 256>>>(Wd, bd, out_logits);
    k_crf<<<8, 256>>>(out_logits, labels, trans, out_ll);
}